// round 4
// baseline (speedup 1.0000x reference)
#include <cuda_runtime.h>
#include <math.h>

#define T_ 256
#define B_ 16
#define E_ 512
#define H_ 2048
#define N_ 14839
#define U_ 48
#define G4H (4*H_)          /* 8192 */
#define EPS_ 1e-6f

/* ---------------- scratch (static __device__, no allocation) ---------------- */
__device__ float g_xh_m[T_*B_*E_];        // (T,B,E)
__device__ float g_xh_c[T_*B_*E_];
__device__ float g_emb[U_*B_*E_];         // gathered embeddings (U*B, E)
__device__ float g_eg[(size_t)U_*B_*G4H]; // emb part of gates + bias, (U*B, 4H)
__device__ float g_gates[B_*G4H];
__device__ float g_h[2][B_*H_];
__device__ float g_c[2][B_*H_];
__device__ float g_ctx[2][B_*E_];
__device__ float g_alpha[2][T_*B_];
__device__ float g_sm[B_*E_];
__device__ float g_sc[B_*E_];
__device__ float g_p[T_*B_];
__device__ float g_u[T_*B_];
__device__ float g_scall[U_*B_*2*E_];     // per-step [s ; ctx], (U*B, 2E)
__device__ float g_wpT[H_*E_];            // W_proj transposed (H,E)
__device__ float g_comb[2*E_*H_];         // [Wm_p ; Wc_p], each (E,H)

/* ---------------- init ---------------- */
__global__ void init_state(float* h, float* c, float* ctx, float* alpha) {
    int i = blockIdx.x * blockDim.x + threadIdx.x;
    if (i < B_*H_) { h[i] = 0.f; c[i] = 0.f; }
    if (i < B_*E_) ctx[i] = 0.f;
    if (i < T_*B_) alpha[i] = (i < B_) ? 1.f : 0.f;   // alpha[t*B+b], t==0 -> 1
}

/* ---------------- embedding gather ---------------- */
__global__ void gather_emb(const float* __restrict__ emb_table,
                           const int* __restrict__ label,
                           float* __restrict__ emb) {
    int r = blockIdx.x;                    // r = u*B + b
    int n = label[r];
    const float* src = emb_table + (size_t)n * E_;
    float* dst = emb + (size_t)r * E_;
    for (int i = threadIdx.x; i < E_; i += blockDim.x) dst[i] = src[i];
}

/* ---------------- transpose (512,2048) -> (2048,512) ---------------- */
__global__ void transposeEH(const float* __restrict__ A, float* __restrict__ At) {
    __shared__ float tile[32][33];
    int x0 = blockIdx.x * 32, y0 = blockIdx.y * 32;   // x: H dim, y: E dim
    int tx = threadIdx.x, ty = threadIdx.y;
    for (int j = 0; j < 32; j += 8)
        tile[ty+j][tx] = A[(size_t)(y0+ty+j) * H_ + x0 + tx];
    __syncthreads();
    for (int j = 0; j < 32; j += 8)
        At[(size_t)(x0+ty+j) * E_ + y0 + tx] = tile[tx][ty+j];
}

/* ---------------- big GEMM: C[m, j] = sum_k W[m,k]*X[j,k] (+bias[m]) ---------------- */
#define BM 128
#define BN 128
#define BK 8
__global__ __launch_bounds__(256) void sgemm_tn(
        const float* __restrict__ W, int ldw,
        const float* __restrict__ X, int ldx,
        const float* __restrict__ bias,
        float* __restrict__ C, size_t ldcw, size_t ldcx,
        int M, int Nx, int K)
{
    __shared__ float Ws[BK][BM+4];
    __shared__ float Xs[BK][BN+4];
    int m0 = blockIdx.y * BM;
    int x0 = blockIdx.x * BN;
    int tid = threadIdx.x;
    int tx = tid & 15, ty = tid >> 4;

    float acc[8][8];
#pragma unroll
    for (int i = 0; i < 8; i++)
#pragma unroll
        for (int j = 0; j < 8; j++) acc[i][j] = 0.f;

    int lrow = tid >> 1;
    int lkq  = (tid & 1) * 4;

    for (int k0 = 0; k0 < K; k0 += BK) {
        float4 v = make_float4(0.f,0.f,0.f,0.f);
        if (m0 + lrow < M)
            v = *(const float4*)(W + (size_t)(m0 + lrow) * ldw + k0 + lkq);
        Ws[lkq+0][lrow] = v.x; Ws[lkq+1][lrow] = v.y;
        Ws[lkq+2][lrow] = v.z; Ws[lkq+3][lrow] = v.w;

        float4 u = make_float4(0.f,0.f,0.f,0.f);
        if (x0 + lrow < Nx)
            u = *(const float4*)(X + (size_t)(x0 + lrow) * ldx + k0 + lkq);
        Xs[lkq+0][lrow] = u.x; Xs[lkq+1][lrow] = u.y;
        Xs[lkq+2][lrow] = u.z; Xs[lkq+3][lrow] = u.w;
        __syncthreads();

#pragma unroll
        for (int kk = 0; kk < BK; kk++) {
            float4 w0 = *(const float4*)&Ws[kk][ty*8];
            float4 w1 = *(const float4*)&Ws[kk][ty*8+4];
            float4 x0v = *(const float4*)&Xs[kk][tx*8];
            float4 x1v = *(const float4*)&Xs[kk][tx*8+4];
            float rw[8] = {w0.x,w0.y,w0.z,w0.w,w1.x,w1.y,w1.z,w1.w};
            float rx[8] = {x0v.x,x0v.y,x0v.z,x0v.w,x1v.x,x1v.y,x1v.z,x1v.w};
#pragma unroll
            for (int i = 0; i < 8; i++)
#pragma unroll
                for (int j = 0; j < 8; j++) acc[i][j] += rw[i] * rx[j];
        }
        __syncthreads();
    }

#pragma unroll
    for (int i = 0; i < 8; i++) {
        int m = m0 + ty*8 + i;
        if (m >= M) continue;
        float bv = bias ? bias[m] : 0.f;
#pragma unroll
        for (int j = 0; j < 8; j++) {
            int xr = x0 + tx*8 + j;
            if (xr < Nx)
                C[(size_t)m * ldcw + (size_t)xr * ldcx] = acc[i][j] + bv;
        }
    }
}

/* ---------------- gates GEMV: one warp per gate-row r in [0, 4H) ----------------
   gates[b, r] = eg_u[b, r] + ctx[b]·W_ih[r, E:2E] + h[b]·W_hh[r, :]
   Plain loops, no unroll pragmas (keeps registers ~40, no spill).               */
__global__ __launch_bounds__(256) void gemv_gates(
        const float* __restrict__ ctx,   // (16, 512)
        const float* __restrict__ h,     // (16, 2048)
        const float* __restrict__ W_ih,  // (8192, 1024)
        const float* __restrict__ W_hh,  // (8192, 2048)
        const float* __restrict__ eg_u,  // (16, 8192)
        float* __restrict__ gates)       // (16, 8192)
{
    int r = (blockIdx.x * blockDim.x + threadIdx.x) >> 5;
    int lane = threadIdx.x & 31;
    if (r >= G4H) return;

    float acc[16];
#pragma unroll
    for (int b = 0; b < 16; b++) acc[b] = 0.f;

    /* ctx part, K = 512 */
    {
        const float* wr = W_ih + (size_t)r * (2*E_) + E_;
        for (int kk = lane*4; kk < E_; kk += 128) {
            float4 wv = *(const float4*)(wr + kk);
#pragma unroll
            for (int b = 0; b < 16; b++) {
                float4 a = *(const float4*)(ctx + b*E_ + kk);
                acc[b] += wv.x*a.x + wv.y*a.y + wv.z*a.z + wv.w*a.w;
            }
        }
    }
    /* h part, K = 2048 */
    {
        const float* wr = W_hh + (size_t)r * H_;
        for (int kk = lane*4; kk < H_; kk += 128) {
            float4 wv = *(const float4*)(wr + kk);
#pragma unroll
            for (int b = 0; b < 16; b++) {
                float4 a = *(const float4*)(h + b*H_ + kk);
                acc[b] += wv.x*a.x + wv.y*a.y + wv.z*a.z + wv.w*a.w;
            }
        }
    }
#pragma unroll
    for (int b = 0; b < 16; b++)
#pragma unroll
        for (int off = 16; off > 0; off >>= 1)
            acc[b] += __shfl_xor_sync(0xffffffffu, acc[b], off);

    if (lane < 16)
        gates[(size_t)lane * G4H + r] = acc[lane] + eg_u[(size_t)lane * G4H + r];
}

/* ---------------- LSTM pointwise ---------------- */
__device__ __forceinline__ float sigm(float x) { return 1.f / (1.f + expf(-x)); }

__global__ void lstm_pointwise(const float* __restrict__ gates,
                               const float* __restrict__ c_in,
                               float* __restrict__ c_out,
                               float* __restrict__ h_out) {
    int i = blockIdx.x * blockDim.x + threadIdx.x;   // B*H
    if (i >= B_*H_) return;
    int b = i >> 11, k = i & (H_-1);
    const float* g = gates + (size_t)b * G4H;
    float gi = g[k], gf = g[H_ + k], gg = g[2*H_ + k], go = g[3*H_ + k];
    float cn = sigm(gf) * c_in[i] + sigm(gi) * tanhf(gg);
    c_out[i] = cn;
    h_out[i] = sigm(go) * tanhf(cn);
}

/* ---------------- triple projection from h_new ----------------
   rows 0..511: s (W_proj), 512..1023: sm (Wm_p), 1024..1535: sc (Wc_p).
   Plain loop, no unroll pragma.                                         */
__global__ __launch_bounds__(256) void proj3(
        const float* __restrict__ h,      // (16, 2048)
        const float* __restrict__ W_proj, // (512, 2048)
        const float* __restrict__ comb,   // (1024, 2048) = [Wm_p ; Wc_p]
        float* __restrict__ sc_u,         // (16, 1024) — s goes in cols [0,512)
        float* __restrict__ sm, float* __restrict__ sc)
{
    int warp = (blockIdx.x * blockDim.x + threadIdx.x) >> 5;  // 0..1535
    int lane = threadIdx.x & 31;
    if (warp >= 3*E_) return;
    const float* Wr = (warp < E_) ? (W_proj + (size_t)warp * H_)
                                  : (comb + (size_t)(warp - E_) * H_);
    float acc[16];
#pragma unroll
    for (int b = 0; b < 16; b++) acc[b] = 0.f;
    for (int kk = lane*4; kk < H_; kk += 128) {
        float4 wv = *(const float4*)(Wr + kk);
#pragma unroll
        for (int b = 0; b < 16; b++) {
            float4 a = *(const float4*)(h + b*H_ + kk);
            acc[b] += wv.x*a.x + wv.y*a.y + wv.z*a.z + wv.w*a.w;
        }
    }
#pragma unroll
    for (int b = 0; b < 16; b++)
#pragma unroll
        for (int off = 16; off > 0; off >>= 1)
            acc[b] += __shfl_xor_sync(0xffffffffu, acc[b], off);
    if (lane < 16) {
        float r = acc[lane];
        if (warp < E_)            sc_u[lane*(2*E_) + warp] = r;
        else if (warp < 2*E_)     sm[lane*E_ + (warp - E_)] = r;
        else                      sc[lane*E_ + (warp - 2*E_)] = r;
    }
}

/* ---------------- monotonic / chunk energies (approx tanh) ---------------- */
__device__ __forceinline__ float tanha(float x) {
    float y;
    asm("tanh.approx.f32 %0, %1;" : "=f"(y) : "f"(x));
    return y;
}

__global__ __launch_bounds__(256) void energies(
        const float* __restrict__ sm, const float* __restrict__ sc,
        const float* __restrict__ xm, const float* __restrict__ xc,
        const float* __restrict__ v_m, const float* __restrict__ v_c,
        const float* __restrict__ r_m, const float* __restrict__ att_mask,
        float* __restrict__ p, float* __restrict__ uu)
{
    int w = (blockIdx.x * blockDim.x + threadIdx.x) >> 5;
    int lane = threadIdx.x & 31;
    if (w >= T_*B_) return;
    int t = w >> 4, b = w & 15;
    const float* xmp = xm + (size_t)(t*B_ + b) * E_;
    const float* xcp = xc + (size_t)(t*B_ + b) * E_;
    const float* smp = sm + (size_t)b * E_;
    const float* scp = sc + (size_t)b * E_;
    float am = 0.f, ac = 0.f;
    for (int e = lane * 4; e < E_; e += 128) {
        float4 a  = *(const float4*)(xmp + e);
        float4 s4 = *(const float4*)(smp + e);
        float4 v4 = *(const float4*)(v_m + e);
        am += v4.x*tanha(a.x+s4.x) + v4.y*tanha(a.y+s4.y)
            + v4.z*tanha(a.z+s4.z) + v4.w*tanha(a.w+s4.w);
        float4 a2  = *(const float4*)(xcp + e);
        float4 s42 = *(const float4*)(scp + e);
        float4 v42 = *(const float4*)(v_c + e);
        ac += v42.x*tanha(a2.x+s42.x) + v42.y*tanha(a2.y+s42.y)
            + v42.z*tanha(a2.z+s42.z) + v42.w*tanha(a2.w+s42.w);
    }
#pragma unroll
    for (int off = 16; off > 0; off >>= 1) {
        am += __shfl_xor_sync(0xffffffffu, am, off);
        ac += __shfl_xor_sync(0xffffffffu, ac, off);
    }
    if (lane == 0) {
        float mk = att_mask[b*T_ + t];
        float e_ = am + r_m[0];
        p[t*B_ + b] = sigm(e_) * mk;
        uu[t*B_ + b] = ac;
    }
}

/* ---------------- per-b scans + ctx reduction ---------------- */
__device__ __forceinline__ float scan_add(float v, float* buf, int t) {
    buf[t] = v; __syncthreads();
#pragma unroll
    for (int off = 1; off < T_; off <<= 1) {
        float x = (t >= off) ? buf[t-off] : 0.f;
        __syncthreads();
        buf[t] += x;
        __syncthreads();
    }
    return buf[t];
}
__device__ __forceinline__ float scan_mul(float v, float* buf, int t) {
    buf[t] = v; __syncthreads();
#pragma unroll
    for (int off = 1; off < T_; off <<= 1) {
        float x = (t >= off) ? buf[t-off] : 1.f;
        __syncthreads();
        buf[t] *= x;
        __syncthreads();
    }
    return buf[t];
}

__global__ __launch_bounds__(256) void scan_ctx(
        const float* __restrict__ p, const float* __restrict__ uu,
        const float* __restrict__ alpha_in, const float* __restrict__ att_mask,
        const float* __restrict__ x,
        float* __restrict__ alpha_out, float* __restrict__ ctx_out,
        float* __restrict__ sc_slot)
{
    __shared__ float bufA[T_], bufB[T_], bufC[T_], bufD[T_], red[T_], sbeta[T_];
    int b = blockIdx.x, t = threadIdx.x;
    float pv = p[t*B_ + b];
    float uv = uu[t*B_ + b];
    float ap = alpha_in[t*B_ + b];
    float mk = att_mask[b*T_ + t];

    red[t] = uv; __syncthreads();
    for (int off = 128; off > 0; off >>= 1) {
        if (t < off) red[t] = fmaxf(red[t], red[t+off]);
        __syncthreads();
    }
    float um = red[0];

    float eu = expf(uv - um) * mk;
    float cs = scan_add(eu, bufA, t);
    float denom = cs - (t >= 8 ? bufA[t-8] : 0.f);

    (void)scan_mul(1.f - pv, bufB, t);
    float cp = (t == 0) ? 1.f : bufB[t-1];

    float q = ap / fmaxf(cp, EPS_);
    float qs = scan_add(q, bufC, t);
    float av = pv * cp * qs;

    float rk = av / fmaxf(denom, EPS_);
    (void)scan_add(rk, bufD, t);
    int hi = (t + 7 > T_-1) ? (T_-1) : (t + 7);
    float bv = eu * (bufD[hi] - (t > 0 ? bufD[t-1] : 0.f));

    alpha_out[t*B_ + b] = av;
    sbeta[t] = bv;
    __syncthreads();

    /* ctx[b, :] = sum_t beta[t] * x[t, b, :] */
    for (int d = t; d < E_; d += 256) {
        const float* xp = x + (size_t)b * E_ + d;
        float acc = 0.f;
#pragma unroll 4
        for (int tt = 0; tt < T_; tt++) acc += sbeta[tt] * xp[(size_t)tt * B_ * E_];
        ctx_out[b*E_ + d] = acc;
        sc_slot[(size_t)b * (2*E_) + E_ + d] = acc;
    }
}

/* ---------------- host launcher ---------------- */
extern "C" void kernel_launch(void* const* d_in, const int* in_sizes, int n_in,
                              void* d_out, int out_size)
{
    const float* x        = (const float*)d_in[0];
    const float* att_mask = (const float*)d_in[1];
    const float* emb_tab  = (const float*)d_in[2];
    const float* W_ih     = (const float*)d_in[3];
    const float* W_hh     = (const float*)d_in[4];
    const float* b_lstm   = (const float*)d_in[5];
    const float* W_proj   = (const float*)d_in[6];
    const float* Ws_m     = (const float*)d_in[7];
    const float* Wh_m     = (const float*)d_in[8];
    const float* v_m      = (const float*)d_in[9];
    const float* r_m      = (const float*)d_in[10];
    const float* Ws_c     = (const float*)d_in[11];
    const float* Wh_c     = (const float*)d_in[12];
    const float* v_c      = (const float*)d_in[13];
    const float* W_am     = (const float*)d_in[14];
    const float* W_lm     = (const float*)d_in[15];
    const int*   label    = (const int*)d_in[16];

    float* out_am = (float*)d_out;
    float* out_lm = out_am + (size_t)N_ * U_ * B_;

    float *xh_m, *xh_c, *emb, *eg, *gates, *hb, *cb, *ctxb, *alb, *sm, *sc, *p, *uu, *scall, *wpT, *comb;
    cudaGetSymbolAddress((void**)&xh_m,  g_xh_m);
    cudaGetSymbolAddress((void**)&xh_c,  g_xh_c);
    cudaGetSymbolAddress((void**)&emb,   g_emb);
    cudaGetSymbolAddress((void**)&eg,    g_eg);
    cudaGetSymbolAddress((void**)&gates, g_gates);
    cudaGetSymbolAddress((void**)&hb,    g_h);
    cudaGetSymbolAddress((void**)&cb,    g_c);
    cudaGetSymbolAddress((void**)&ctxb,  g_ctx);
    cudaGetSymbolAddress((void**)&alb,   g_alpha);
    cudaGetSymbolAddress((void**)&sm,    g_sm);
    cudaGetSymbolAddress((void**)&sc,    g_sc);
    cudaGetSymbolAddress((void**)&p,     g_p);
    cudaGetSymbolAddress((void**)&uu,    g_u);
    cudaGetSymbolAddress((void**)&scall, g_scall);
    cudaGetSymbolAddress((void**)&wpT,   g_wpT);
    cudaGetSymbolAddress((void**)&comb,  g_comb);

    /* init recurrent state (buffer 0) */
    init_state<<<(B_*H_ + 255)/256, 256>>>(hb, cb, ctxb, alb);

    /* gather teacher-forced embeddings */
    gather_emb<<<U_*B_, 128>>>(emb_tab, label, emb);

    /* xh_m = x @ Wh_m^T ; xh_c = x @ Wh_c^T  (out[tb*E + e]) */
    sgemm_tn<<<dim3((T_*B_)/BN, (E_+BM-1)/BM), 256>>>(Wh_m, E_, x, E_, nullptr,
            xh_m, 1, E_, E_, T_*B_, E_);
    sgemm_tn<<<dim3((T_*B_)/BN, (E_+BM-1)/BM), 256>>>(Wh_c, E_, x, E_, nullptr,
            xh_c, 1, E_, E_, T_*B_, E_);

    /* eg[ub, j] = emb[ub] @ W_ih[:, :E]^T + b_lstm */
    sgemm_tn<<<dim3((U_*B_)/BN, G4H/BM), 256>>>(W_ih, 2*E_, emb, E_, b_lstm,
            eg, 1, G4H, G4H, U_*B_, E_);

    /* lm output: out_lm[n*768 + ub] */
    sgemm_tn<<<dim3((U_*B_)/BN, (N_+BM-1)/BM), 256>>>(W_lm, E_, emb, E_, nullptr,
            out_lm, U_*B_, 1, N_, U_*B_, E_);

    /* folded projections: Wm_p = Ws_m @ W_proj, Wc_p = Ws_c @ W_proj */
    transposeEH<<<dim3(H_/32, E_/32), dim3(32, 8)>>>(W_proj, wpT);
    sgemm_tn<<<dim3(H_/BN, E_/BM), 256>>>(Ws_m, E_, wpT, E_, nullptr,
            comb, H_, 1, E_, H_, E_);
    sgemm_tn<<<dim3(H_/BN, E_/BM), 256>>>(Ws_c, E_, wpT, E_, nullptr,
            comb + (size_t)E_*H_, H_, 1, E_, H_, E_);

    for (int u = 0; u < U_; u++) {
        int in = u & 1, out = in ^ 1;
        const float* h_in   = hb   + (size_t)in  * B_*H_;
        float*       h_out  = hb   + (size_t)out * B_*H_;
        const float* c_in   = cb   + (size_t)in  * B_*H_;
        float*       c_out  = cb   + (size_t)out * B_*H_;
        const float* ctx_in = ctxb + (size_t)in  * B_*E_;
        float*       ctx_out= ctxb + (size_t)out * B_*E_;
        const float* al_in  = alb  + (size_t)in  * T_*B_;
        float*       al_out = alb  + (size_t)out * T_*B_;
        float*       sc_u   = scall + (size_t)u * B_ * 2*E_;
        const float* eg_u   = eg    + (size_t)u * B_ * G4H;

        gemv_gates<<<G4H/8, 256>>>(ctx_in, h_in, W_ih, W_hh, eg_u, gates);
        lstm_pointwise<<<(B_*H_)/256, 256>>>(gates, c_in, c_out, h_out);
        proj3<<<(3*E_)/8, 256>>>(h_out, W_proj, comb, sc_u, sm, sc);
        energies<<<(T_*B_)/8, 256>>>(sm, sc, xh_m, xh_c, v_m, v_c, r_m, att_mask, p, uu);
        scan_ctx<<<B_, T_>>>(p, uu, al_in, att_mask, x, al_out, ctx_out, sc_u);
    }

    /* am output: out_am[n*768 + ub] = [s;ctx] @ W_am[n]^T */
    sgemm_tn<<<dim3((U_*B_)/BN, (N_+BM-1)/BM), 256>>>(W_am, 2*E_, scall, 2*E_, nullptr,
            out_am, U_*B_, 1, N_, U_*B_, 2*E_);
}

// round 5
// speedup vs baseline: 1.1427x; 1.1427x over previous
#include <cuda_runtime.h>
#include <cuda_bf16.h>
#include <math.h>

#define T_ 256
#define B_ 16
#define E_ 512
#define H_ 2048
#define N_ 14839
#define U_ 48
#define G4H (4*H_)          /* 8192 */
#define EPS_ 1e-6f

/* ---------------- scratch (static __device__, no allocation) ---------------- */
__device__ float g_xh_m[T_*B_*E_];        // (T,B,E)
__device__ float g_xh_c[T_*B_*E_];
__device__ float g_emb[U_*B_*E_];         // gathered embeddings (U*B, E)
__device__ float g_eg[(size_t)U_*B_*G4H]; // emb part of gates + bias, (U*B, 4H)
__device__ float g_gates[B_*G4H];
__device__ float g_h[2][B_*H_];
__device__ float g_c[2][B_*H_];
__device__ float g_ctx[2][B_*E_];
__device__ float g_alpha[2][T_*B_];
__device__ float g_sm[B_*E_];
__device__ float g_sc[B_*E_];
__device__ float g_p[T_*B_];
__device__ float g_u[T_*B_];
__device__ float g_scall[U_*B_*2*E_];     // per-step [s ; ctx], (U*B, 2E)

/* bf16 weight copies (converted once per launch) */
__device__ __nv_bfloat16 g_whh_bf[(size_t)G4H*H_];   // (8192, 2048)
__device__ __nv_bfloat16 g_wihc_bf[(size_t)G4H*E_];  // ctx half, packed dense (8192, 512)
__device__ __nv_bfloat16 g_wproj_bf[E_*H_];          // (512, 2048)
__device__ __nv_bfloat16 g_wsm_bf[E_*E_];            // (512, 512)
__device__ __nv_bfloat16 g_wsc_bf[E_*E_];            // (512, 512)

/* ---------------- init ---------------- */
__global__ void init_state(float* h, float* c, float* ctx, float* alpha) {
    int i = blockIdx.x * blockDim.x + threadIdx.x;
    if (i < B_*H_) { h[i] = 0.f; c[i] = 0.f; }
    if (i < B_*E_) ctx[i] = 0.f;
    if (i < T_*B_) alpha[i] = (i < B_) ? 1.f : 0.f;   // alpha[t*B+b], t==0 -> 1
}

/* ---------------- fp32 -> bf16 conversions ---------------- */
__global__ void f2bf(const float* __restrict__ src, __nv_bfloat16* __restrict__ dst, size_t n) {
    size_t i = (size_t)blockIdx.x * blockDim.x + threadIdx.x;
    if (i < n) dst[i] = __float2bfloat16(src[i]);
}
/* gather strided columns [off, off+cols) of each row into dense bf16 */
__global__ void f2bf_strided(const float* __restrict__ src, int ld, int off,
                             __nv_bfloat16* __restrict__ dst, int cols, size_t n) {
    size_t i = (size_t)blockIdx.x * blockDim.x + threadIdx.x;
    if (i >= n) return;
    size_t r = i / cols, c = i % cols;
    dst[i] = __float2bfloat16(src[r * (size_t)ld + off + c]);
}

/* ---------------- embedding gather ---------------- */
__global__ void gather_emb(const float* __restrict__ emb_table,
                           const int* __restrict__ label,
                           float* __restrict__ emb) {
    int r = blockIdx.x;                    // r = u*B + b
    int n = label[r];
    const float* src = emb_table + (size_t)n * E_;
    float* dst = emb + (size_t)r * E_;
    for (int i = threadIdx.x; i < E_; i += blockDim.x) dst[i] = src[i];
}

/* ---------------- big GEMM: C[m, j] = sum_k W[m,k]*X[j,k] (+bias[m]) ---------------- */
#define BM 128
#define BN 128
#define BK 8
__global__ __launch_bounds__(256) void sgemm_tn(
        const float* __restrict__ W, int ldw,
        const float* __restrict__ X, int ldx,
        const float* __restrict__ bias,
        float* __restrict__ C, size_t ldcw, size_t ldcx,
        int M, int Nx, int K)
{
    __shared__ float Ws[BK][BM+4];
    __shared__ float Xs[BK][BN+4];
    int m0 = blockIdx.y * BM;
    int x0 = blockIdx.x * BN;
    int tid = threadIdx.x;
    int tx = tid & 15, ty = tid >> 4;

    float acc[8][8];
#pragma unroll
    for (int i = 0; i < 8; i++)
#pragma unroll
        for (int j = 0; j < 8; j++) acc[i][j] = 0.f;

    int lrow = tid >> 1;
    int lkq  = (tid & 1) * 4;

    for (int k0 = 0; k0 < K; k0 += BK) {
        float4 v = make_float4(0.f,0.f,0.f,0.f);
        if (m0 + lrow < M)
            v = *(const float4*)(W + (size_t)(m0 + lrow) * ldw + k0 + lkq);
        Ws[lkq+0][lrow] = v.x; Ws[lkq+1][lrow] = v.y;
        Ws[lkq+2][lrow] = v.z; Ws[lkq+3][lrow] = v.w;

        float4 u = make_float4(0.f,0.f,0.f,0.f);
        if (x0 + lrow < Nx)
            u = *(const float4*)(X + (size_t)(x0 + lrow) * ldx + k0 + lkq);
        Xs[lkq+0][lrow] = u.x; Xs[lkq+1][lrow] = u.y;
        Xs[lkq+2][lrow] = u.z; Xs[lkq+3][lrow] = u.w;
        __syncthreads();

#pragma unroll
        for (int kk = 0; kk < BK; kk++) {
            float4 w0 = *(const float4*)&Ws[kk][ty*8];
            float4 w1 = *(const float4*)&Ws[kk][ty*8+4];
            float4 x0v = *(const float4*)&Xs[kk][tx*8];
            float4 x1v = *(const float4*)&Xs[kk][tx*8+4];
            float rw[8] = {w0.x,w0.y,w0.z,w0.w,w1.x,w1.y,w1.z,w1.w};
            float rx[8] = {x0v.x,x0v.y,x0v.z,x0v.w,x1v.x,x1v.y,x1v.z,x1v.w};
#pragma unroll
            for (int i = 0; i < 8; i++)
#pragma unroll
                for (int j = 0; j < 8; j++) acc[i][j] += rw[i] * rx[j];
        }
        __syncthreads();
    }

#pragma unroll
    for (int i = 0; i < 8; i++) {
        int m = m0 + ty*8 + i;
        if (m >= M) continue;
        float bv = bias ? bias[m] : 0.f;
#pragma unroll
        for (int j = 0; j < 8; j++) {
            int xr = x0 + tx*8 + j;
            if (xr < Nx)
                C[(size_t)m * ldcw + (size_t)xr * ldcx] = acc[i][j] + bv;
        }
    }
}

/* ---------------- batch-16 GEMV, bf16 weights, fp32 activations ----------------
   C[b,n] = (C0[b,n]) + sum_k A[b,k] * W[n,k].  One warp per output row n.
   Each lane loads 8 bf16 weights (16B) per iteration; plain loop, no pragmas. */
__global__ __launch_bounds__(256) void gemv16b(
        const float* __restrict__ A, int lda, int K,
        const __nv_bfloat16* __restrict__ W, int ldw,
        const float* __restrict__ C0, int ldc0,
        float* __restrict__ C, int ldc, int N)
{
    int warp = (blockIdx.x * blockDim.x + threadIdx.x) >> 5;
    int lane = threadIdx.x & 31;
    if (warp >= N) return;
    const __nv_bfloat16* Wr = W + (size_t)warp * ldw;
    float acc[16];
#pragma unroll
    for (int b = 0; b < 16; b++) acc[b] = 0.f;

    for (int k = lane * 8; k < K; k += 256) {
        float4 wraw = *(const float4*)(Wr + k);   // 8 bf16
        const __nv_bfloat162* wp = (const __nv_bfloat162*)&wraw;
        float2 w0 = __bfloat1622float2(wp[0]);
        float2 w1 = __bfloat1622float2(wp[1]);
        float2 w2 = __bfloat1622float2(wp[2]);
        float2 w3 = __bfloat1622float2(wp[3]);
#pragma unroll
        for (int b = 0; b < 16; b++) {
            const float* ab = A + (size_t)b * lda + k;
            float4 a0 = *(const float4*)(ab);
            float4 a1 = *(const float4*)(ab + 4);
            acc[b] += w0.x*a0.x + w0.y*a0.y + w1.x*a0.z + w1.y*a0.w
                    + w2.x*a1.x + w2.y*a1.y + w3.x*a1.z + w3.y*a1.w;
        }
    }
#pragma unroll
    for (int b = 0; b < 16; b++) {
#pragma unroll
        for (int off = 16; off > 0; off >>= 1)
            acc[b] += __shfl_xor_sync(0xffffffffu, acc[b], off);
    }
    if (lane < 16) {
        float r = 0.f;
#pragma unroll
        for (int b = 0; b < 16; b++) if (lane == b) r = acc[b];
        if (C0) r += C0[(size_t)lane * ldc0 + warp];
        C[(size_t)lane * ldc + warp] = r;
    }
}

/* ---------------- LSTM pointwise ---------------- */
__device__ __forceinline__ float sigm(float x) { return 1.f / (1.f + expf(-x)); }

__global__ void lstm_pointwise(const float* __restrict__ gates,
                               const float* __restrict__ c_in,
                               float* __restrict__ c_out,
                               float* __restrict__ h_out) {
    int i = blockIdx.x * blockDim.x + threadIdx.x;   // B*H
    if (i >= B_*H_) return;
    int b = i >> 11, k = i & (H_-1);
    const float* g = gates + (size_t)b * G4H;
    float gi = g[k], gf = g[H_ + k], gg = g[2*H_ + k], go = g[3*H_ + k];
    float cn = sigm(gf) * c_in[i] + sigm(gi) * tanhf(gg);
    c_out[i] = cn;
    h_out[i] = sigm(go) * tanhf(cn);
}

/* ---------------- monotonic / chunk energies (approx tanh) ---------------- */
__device__ __forceinline__ float tanha(float x) {
    float y;
    asm("tanh.approx.f32 %0, %1;" : "=f"(y) : "f"(x));
    return y;
}

__global__ __launch_bounds__(256) void energies(
        const float* __restrict__ sm, const float* __restrict__ sc,
        const float* __restrict__ xm, const float* __restrict__ xc,
        const float* __restrict__ v_m, const float* __restrict__ v_c,
        const float* __restrict__ r_m, const float* __restrict__ att_mask,
        float* __restrict__ p, float* __restrict__ uu)
{
    int w = (blockIdx.x * blockDim.x + threadIdx.x) >> 5;
    int lane = threadIdx.x & 31;
    if (w >= T_*B_) return;
    int t = w >> 4, b = w & 15;
    const float* xmp = xm + (size_t)(t*B_ + b) * E_;
    const float* xcp = xc + (size_t)(t*B_ + b) * E_;
    const float* smp = sm + (size_t)b * E_;
    const float* scp = sc + (size_t)b * E_;
    float am = 0.f, ac = 0.f;
    for (int e = lane * 4; e < E_; e += 128) {
        float4 a  = *(const float4*)(xmp + e);
        float4 s4 = *(const float4*)(smp + e);
        float4 v4 = *(const float4*)(v_m + e);
        am += v4.x*tanha(a.x+s4.x) + v4.y*tanha(a.y+s4.y)
            + v4.z*tanha(a.z+s4.z) + v4.w*tanha(a.w+s4.w);
        float4 a2  = *(const float4*)(xcp + e);
        float4 s42 = *(const float4*)(scp + e);
        float4 v42 = *(const float4*)(v_c + e);
        ac += v42.x*tanha(a2.x+s42.x) + v42.y*tanha(a2.y+s42.y)
            + v42.z*tanha(a2.z+s42.z) + v42.w*tanha(a2.w+s42.w);
    }
#pragma unroll
    for (int off = 16; off > 0; off >>= 1) {
        am += __shfl_xor_sync(0xffffffffu, am, off);
        ac += __shfl_xor_sync(0xffffffffu, ac, off);
    }
    if (lane == 0) {
        float mk = att_mask[b*T_ + t];
        float e_ = am + r_m[0];
        p[t*B_ + b] = sigm(e_) * mk;
        uu[t*B_ + b] = ac;
    }
}

/* ---------------- per-b scans + ctx reduction (fused) ---------------- */
__device__ __forceinline__ float scan_add(float v, float* buf, int t) {
    buf[t] = v; __syncthreads();
#pragma unroll
    for (int off = 1; off < T_; off <<= 1) {
        float x = (t >= off) ? buf[t-off] : 0.f;
        __syncthreads();
        buf[t] += x;
        __syncthreads();
    }
    return buf[t];
}
__device__ __forceinline__ float scan_mul(float v, float* buf, int t) {
    buf[t] = v; __syncthreads();
#pragma unroll
    for (int off = 1; off < T_; off <<= 1) {
        float x = (t >= off) ? buf[t-off] : 1.f;
        __syncthreads();
        buf[t] *= x;
        __syncthreads();
    }
    return buf[t];
}

__global__ __launch_bounds__(256) void scan_ctx(
        const float* __restrict__ p, const float* __restrict__ uu,
        const float* __restrict__ alpha_in, const float* __restrict__ att_mask,
        const float* __restrict__ x,
        float* __restrict__ alpha_out, float* __restrict__ ctx_out,
        float* __restrict__ sc_slot)
{
    __shared__ float bufA[T_], bufB[T_], bufC[T_], bufD[T_], red[T_], sbeta[T_];
    int b = blockIdx.x, t = threadIdx.x;
    float pv = p[t*B_ + b];
    float uv = uu[t*B_ + b];
    float ap = alpha_in[t*B_ + b];
    float mk = att_mask[b*T_ + t];

    red[t] = uv; __syncthreads();
    for (int off = 128; off > 0; off >>= 1) {
        if (t < off) red[t] = fmaxf(red[t], red[t+off]);
        __syncthreads();
    }
    float um = red[0];

    float eu = expf(uv - um) * mk;
    float cs = scan_add(eu, bufA, t);
    float denom = cs - (t >= 8 ? bufA[t-8] : 0.f);

    (void)scan_mul(1.f - pv, bufB, t);
    float cp = (t == 0) ? 1.f : bufB[t-1];

    float q = ap / fmaxf(cp, EPS_);
    float qs = scan_add(q, bufC, t);
    float av = pv * cp * qs;

    float rk = av / fmaxf(denom, EPS_);
    (void)scan_add(rk, bufD, t);
    int hi = (t + 7 > T_-1) ? (T_-1) : (t + 7);
    float bv = eu * (bufD[hi] - (t > 0 ? bufD[t-1] : 0.f));

    alpha_out[t*B_ + b] = av;
    sbeta[t] = bv;
    __syncthreads();

    /* ctx[b, :] = sum_t beta[t] * x[t, b, :] */
    for (int d = t; d < E_; d += 256) {
        const float* xp = x + (size_t)b * E_ + d;
        float acc = 0.f;
#pragma unroll 4
        for (int tt = 0; tt < T_; tt++) acc += sbeta[tt] * xp[(size_t)tt * B_ * E_];
        ctx_out[b*E_ + d] = acc;
        sc_slot[(size_t)b * (2*E_) + E_ + d] = acc;
    }
}

/* ---------------- host launcher ---------------- */
extern "C" void kernel_launch(void* const* d_in, const int* in_sizes, int n_in,
                              void* d_out, int out_size)
{
    const float* x        = (const float*)d_in[0];
    const float* att_mask = (const float*)d_in[1];
    const float* emb_tab  = (const float*)d_in[2];
    const float* W_ih     = (const float*)d_in[3];
    const float* W_hh     = (const float*)d_in[4];
    const float* b_lstm   = (const float*)d_in[5];
    const float* W_proj   = (const float*)d_in[6];
    const float* Ws_m     = (const float*)d_in[7];
    const float* Wh_m     = (const float*)d_in[8];
    const float* v_m      = (const float*)d_in[9];
    const float* r_m      = (const float*)d_in[10];
    const float* Ws_c     = (const float*)d_in[11];
    const float* Wh_c     = (const float*)d_in[12];
    const float* v_c      = (const float*)d_in[13];
    const float* W_am     = (const float*)d_in[14];
    const float* W_lm     = (const float*)d_in[15];
    const int*   label    = (const int*)d_in[16];

    float* out_am = (float*)d_out;
    float* out_lm = out_am + (size_t)N_ * U_ * B_;

    float *xh_m, *xh_c, *emb, *eg, *gates, *hb, *cb, *ctxb, *alb, *sm, *sc, *p, *uu, *scall;
    __nv_bfloat16 *whh_bf, *wihc_bf, *wproj_bf, *wsm_bf, *wsc_bf;
    cudaGetSymbolAddress((void**)&xh_m,  g_xh_m);
    cudaGetSymbolAddress((void**)&xh_c,  g_xh_c);
    cudaGetSymbolAddress((void**)&emb,   g_emb);
    cudaGetSymbolAddress((void**)&eg,    g_eg);
    cudaGetSymbolAddress((void**)&gates, g_gates);
    cudaGetSymbolAddress((void**)&hb,    g_h);
    cudaGetSymbolAddress((void**)&cb,    g_c);
    cudaGetSymbolAddress((void**)&ctxb,  g_ctx);
    cudaGetSymbolAddress((void**)&alb,   g_alpha);
    cudaGetSymbolAddress((void**)&sm,    g_sm);
    cudaGetSymbolAddress((void**)&sc,    g_sc);
    cudaGetSymbolAddress((void**)&p,     g_p);
    cudaGetSymbolAddress((void**)&uu,    g_u);
    cudaGetSymbolAddress((void**)&scall, g_scall);
    cudaGetSymbolAddress((void**)&whh_bf,   g_whh_bf);
    cudaGetSymbolAddress((void**)&wihc_bf,  g_wihc_bf);
    cudaGetSymbolAddress((void**)&wproj_bf, g_wproj_bf);
    cudaGetSymbolAddress((void**)&wsm_bf,   g_wsm_bf);
    cudaGetSymbolAddress((void**)&wsc_bf,   g_wsc_bf);

    /* init recurrent state (buffer 0) */
    init_state<<<(B_*H_ + 255)/256, 256>>>(hb, cb, ctxb, alb);

    /* bf16 weight conversions (once) */
    {
        size_t n;
        n = (size_t)G4H*H_; f2bf<<<(int)((n+511)/512), 512>>>(W_hh, whh_bf, n);
        n = (size_t)G4H*E_; f2bf_strided<<<(int)((n+511)/512), 512>>>(W_ih, 2*E_, E_, wihc_bf, E_, n);
        n = (size_t)E_*H_;  f2bf<<<(int)((n+511)/512), 512>>>(W_proj, wproj_bf, n);
        n = (size_t)E_*E_;  f2bf<<<(int)((n+511)/512), 512>>>(Ws_m, wsm_bf, n);
        n = (size_t)E_*E_;  f2bf<<<(int)((n+511)/512), 512>>>(Ws_c, wsc_bf, n);
    }

    /* gather teacher-forced embeddings */
    gather_emb<<<U_*B_, 128>>>(emb_tab, label, emb);

    /* xh_m = x @ Wh_m^T ; xh_c = x @ Wh_c^T  (out[tb*E + e]) */
    sgemm_tn<<<dim3((T_*B_)/BN, (E_+BM-1)/BM), 256>>>(Wh_m, E_, x, E_, nullptr,
            xh_m, 1, E_, E_, T_*B_, E_);
    sgemm_tn<<<dim3((T_*B_)/BN, (E_+BM-1)/BM), 256>>>(Wh_c, E_, x, E_, nullptr,
            xh_c, 1, E_, E_, T_*B_, E_);

    /* eg[ub, j] = emb[ub] @ W_ih[:, :E]^T + b_lstm */
    sgemm_tn<<<dim3((U_*B_)/BN, G4H/BM), 256>>>(W_ih, 2*E_, emb, E_, b_lstm,
            eg, 1, G4H, G4H, U_*B_, E_);

    /* lm output: out_lm[n*768 + ub] */
    sgemm_tn<<<dim3((U_*B_)/BN, (N_+BM-1)/BM), 256>>>(W_lm, E_, emb, E_, nullptr,
            out_lm, U_*B_, 1, N_, U_*B_, E_);

    for (int u = 0; u < U_; u++) {
        int in = u & 1, out = in ^ 1;
        const float* h_in   = hb   + (size_t)in  * B_*H_;
        float*       h_out  = hb   + (size_t)out * B_*H_;
        const float* c_in   = cb   + (size_t)in  * B_*H_;
        float*       c_out  = cb   + (size_t)out * B_*H_;
        const float* ctx_in = ctxb + (size_t)in  * B_*E_;
        float*       ctx_out= ctxb + (size_t)out * B_*E_;
        const float* al_in  = alb  + (size_t)in  * T_*B_;
        float*       al_out = alb  + (size_t)out * T_*B_;
        float*       sc_u   = scall + (size_t)u * B_ * 2*E_;
        const float* eg_u   = eg    + (size_t)u * B_ * G4H;

        /* gates = eg_u + ctx @ Wih_ctx^T */
        gemv16b<<<G4H/8, 256>>>(ctx_in, E_, E_, wihc_bf, E_,
                                eg_u, G4H, gates, G4H, G4H);
        /* gates += h @ W_hh^T */
        gemv16b<<<G4H/8, 256>>>(h_in, H_, H_, whh_bf, H_,
                                gates, G4H, gates, G4H, G4H);
        /* LSTM cell */
        lstm_pointwise<<<(B_*H_)/256, 256>>>(gates, c_in, c_out, h_out);
        /* s = h_new @ W_proj^T  -> scall[u][:, 0:E] */
        gemv16b<<<E_/8, 256>>>(h_out, H_, H_, wproj_bf, H_,
                               nullptr, 0, sc_u, 2*E_, E_);
        /* sm = s @ Ws_m^T ; sc = s @ Ws_c^T */
        gemv16b<<<E_/8, 256>>>(sc_u, 2*E_, E_, wsm_bf, E_, nullptr, 0, sm, E_, E_);
        gemv16b<<<E_/8, 256>>>(sc_u, 2*E_, E_, wsc_bf, E_, nullptr, 0, sc, E_, E_);
        /* energies -> p, u */
        energies<<<(T_*B_)/8, 256>>>(sm, sc, xh_m, xh_c, v_m, v_c, r_m, att_mask, p, uu);
        /* alpha recursion + beta + ctx (fused) */
        scan_ctx<<<B_, T_>>>(p, uu, al_in, att_mask, x, al_out, ctx_out, sc_u);
    }

    /* am output: out_am[n*768 + ub] = [s;ctx] @ W_am[n]^T */
    sgemm_tn<<<dim3((U_*B_)/BN, (N_+BM-1)/BM), 256>>>(W_am, 2*E_, scall, 2*E_, nullptr,
            out_am, U_*B_, 1, N_, U_*B_, 2*E_);
}

// round 6
// speedup vs baseline: 1.5135x; 1.3245x over previous
#include <cuda_runtime.h>
#include <cuda_bf16.h>
#include <math.h>

#define T_ 256
#define B_ 16
#define E_ 512
#define H_ 2048
#define N_ 14839
#define U_ 48
#define G4H 8192
#define EPS_ 1e-6f
#define NT 256
#define GRID 256

/* ---------------- scratch ---------------- */
__device__ float g_xh_m[T_*B_*E_];
__device__ float g_xh_c[T_*B_*E_];
__device__ float g_emb[U_*B_*E_];
__device__ float g_eg[(size_t)U_*B_*G4H];
__device__ float g_gates[(size_t)B_*G4H];
__device__ float g_h[2][B_*H_];
__device__ float g_c[2][B_*H_];
__device__ float g_alpha[2][T_*B_];
__device__ float g_sm[B_*E_];
__device__ float g_sc[B_*E_];
__device__ float g_p[T_*B_];
__device__ float g_u[T_*B_];
__device__ float g_beta[T_*B_];
__device__ float g_scall[U_*B_*2*E_];
__device__ float g_wpT[H_*E_];
__device__ float g_comb[2*E_*H_];          // fp32 folded [Ws_m@W_proj ; Ws_c@W_proj]
__device__ __nv_bfloat16 g_whh_bf[(size_t)G4H*H_];
__device__ __nv_bfloat16 g_wihc_bf[(size_t)G4H*E_];
__device__ __nv_bfloat16 g_hbf[B_*H_];
__device__ __nv_bfloat16 g_ctxbf[B_*E_];

/* grid barrier state */
__device__ unsigned g_cnt = 0;
__device__ volatile unsigned g_gen = 0;

__device__ __forceinline__ void gbar() {
    __syncthreads();
    if (threadIdx.x == 0) {
        unsigned gen = g_gen;
        __threadfence();
        if (atomicAdd(&g_cnt, 1u) == gridDim.x - 1u) {
            g_cnt = 0;
            __threadfence();
            g_gen = gen + 1u;
        } else {
            while (g_gen == gen) __nanosleep(32);
        }
        __threadfence();   /* gpu-scope fence -> CCTL.IVALL: drop stale L1 lines */
    }
    __syncthreads();
}

__device__ __forceinline__ float sigm(float x) { return 1.f / (1.f + expf(-x)); }
__device__ __forceinline__ float tanha(float x) {
    float y; asm("tanh.approx.f32 %0, %1;" : "=f"(y) : "f"(x)); return y;
}
__device__ __forceinline__ void bf8(float4 raw, float* o) {
    const __nv_bfloat162* p = (const __nv_bfloat162*)&raw;
    float2 a = __bfloat1622float2(p[0]); float2 b = __bfloat1622float2(p[1]);
    float2 c = __bfloat1622float2(p[2]); float2 d = __bfloat1622float2(p[3]);
    o[0]=a.x;o[1]=a.y;o[2]=b.x;o[3]=b.y;o[4]=c.x;o[5]=c.y;o[6]=d.x;o[7]=d.y;
}

/* ---------------- init ---------------- */
__global__ void init_state(float* h, float* c, float* alpha,
                           __nv_bfloat16* hbf, __nv_bfloat16* ctxbf) {
    int i = blockIdx.x * blockDim.x + threadIdx.x;
    if (i < 2*B_*H_) { h[i] = 0.f; c[i] = 0.f; }
    if (i < B_*H_)   hbf[i] = __float2bfloat16(0.f);
    if (i < B_*E_)   ctxbf[i] = __float2bfloat16(0.f);
    if (i < T_*B_)   alpha[i] = (i < B_) ? 1.f : 0.f;
}

/* ---------------- conversions ---------------- */
__global__ void f2bf(const float* __restrict__ src, __nv_bfloat16* __restrict__ dst, size_t n) {
    size_t i = (size_t)blockIdx.x * blockDim.x + threadIdx.x;
    if (i < n) dst[i] = __float2bfloat16(src[i]);
}
__global__ void f2bf_strided(const float* __restrict__ src, int ld, int off,
                             __nv_bfloat16* __restrict__ dst, int cols, size_t n) {
    size_t i = (size_t)blockIdx.x * blockDim.x + threadIdx.x;
    if (i >= n) return;
    size_t r = i / cols, c = i % cols;
    dst[i] = __float2bfloat16(src[r * (size_t)ld + off + c]);
}

/* ---------------- embedding gather ---------------- */
__global__ void gather_emb(const float* __restrict__ emb_table,
                           const int* __restrict__ label,
                           float* __restrict__ emb) {
    int r = blockIdx.x;
    int n = label[r];
    const float* src = emb_table + (size_t)n * E_;
    float* dst = emb + (size_t)r * E_;
    for (int i = threadIdx.x; i < E_; i += blockDim.x) dst[i] = src[i];
}

/* ---------------- transpose (512,2048) -> (2048,512) ---------------- */
__global__ void transposeEH(const float* __restrict__ A, float* __restrict__ At) {
    __shared__ float tile[32][33];
    int x0 = blockIdx.x * 32, y0 = blockIdx.y * 32;
    int tx = threadIdx.x, ty = threadIdx.y;
    for (int j = 0; j < 32; j += 8)
        tile[ty+j][tx] = A[(size_t)(y0+ty+j) * H_ + x0 + tx];
    __syncthreads();
    for (int j = 0; j < 32; j += 8)
        At[(size_t)(x0+ty+j) * E_ + y0 + tx] = tile[tx][ty+j];
}

/* ---------------- big GEMM ---------------- */
#define BM 128
#define BN 128
#define BK 8
__global__ __launch_bounds__(256) void sgemm_tn(
        const float* __restrict__ W, int ldw,
        const float* __restrict__ X, int ldx,
        const float* __restrict__ bias,
        float* __restrict__ C, size_t ldcw, size_t ldcx,
        int M, int Nx, int K)
{
    __shared__ float Ws[BK][BM+4];
    __shared__ float Xs[BK][BN+4];
    int m0 = blockIdx.y * BM;
    int x0 = blockIdx.x * BN;
    int tid = threadIdx.x;
    int tx = tid & 15, ty = tid >> 4;

    float acc[8][8];
#pragma unroll
    for (int i = 0; i < 8; i++)
#pragma unroll
        for (int j = 0; j < 8; j++) acc[i][j] = 0.f;

    int lrow = tid >> 1;
    int lkq  = (tid & 1) * 4;

    for (int k0 = 0; k0 < K; k0 += BK) {
        float4 v = make_float4(0.f,0.f,0.f,0.f);
        if (m0 + lrow < M)
            v = *(const float4*)(W + (size_t)(m0 + lrow) * ldw + k0 + lkq);
        Ws[lkq+0][lrow] = v.x; Ws[lkq+1][lrow] = v.y;
        Ws[lkq+2][lrow] = v.z; Ws[lkq+3][lrow] = v.w;

        float4 u = make_float4(0.f,0.f,0.f,0.f);
        if (x0 + lrow < Nx)
            u = *(const float4*)(X + (size_t)(x0 + lrow) * ldx + k0 + lkq);
        Xs[lkq+0][lrow] = u.x; Xs[lkq+1][lrow] = u.y;
        Xs[lkq+2][lrow] = u.z; Xs[lkq+3][lrow] = u.w;
        __syncthreads();

#pragma unroll
        for (int kk = 0; kk < BK; kk++) {
            float4 w0 = *(const float4*)&Ws[kk][ty*8];
            float4 w1 = *(const float4*)&Ws[kk][ty*8+4];
            float4 x0v = *(const float4*)&Xs[kk][tx*8];
            float4 x1v = *(const float4*)&Xs[kk][tx*8+4];
            float rw[8] = {w0.x,w0.y,w0.z,w0.w,w1.x,w1.y,w1.z,w1.w};
            float rx[8] = {x0v.x,x0v.y,x0v.z,x0v.w,x1v.x,x1v.y,x1v.z,x1v.w};
#pragma unroll
            for (int i = 0; i < 8; i++)
#pragma unroll
                for (int j = 0; j < 8; j++) acc[i][j] += rw[i] * rx[j];
        }
        __syncthreads();
    }

#pragma unroll
    for (int i = 0; i < 8; i++) {
        int m = m0 + ty*8 + i;
        if (m >= M) continue;
        float bv = bias ? bias[m] : 0.f;
#pragma unroll
        for (int j = 0; j < 8; j++) {
            int xr = x0 + tx*8 + j;
            if (xr < Nx)
                C[(size_t)m * ldcw + (size_t)xr * ldcx] = acc[i][j] + bv;
        }
    }
}

/* ================ PERSISTENT DECODER LOOP ================ */
__global__ __launch_bounds__(NT) void decoder_loop(
        const float* __restrict__ x, const float* __restrict__ mask,
        const __nv_bfloat16* __restrict__ whh, const __nv_bfloat16* __restrict__ wihc,
        const float* __restrict__ wproj, const float* __restrict__ comb,
        const float* __restrict__ eg,
        const float* __restrict__ v_m, const float* __restrict__ v_c,
        const float* __restrict__ r_m,
        const float* __restrict__ xh_m, const float* __restrict__ xh_c,
        float* gates, float* hb, float* cb, float* alb,
        __nv_bfloat16* hbf, __nv_bfloat16* ctxbf,
        float* smv, float* scv, float* pv, float* uvv, float* betav,
        float* scall)
{
    __shared__ float shA[T_], shB[T_], shC[T_], shD[T_], shR[T_];
    int tid = threadIdx.x;
    int lane = tid & 31;
    int gw = blockIdx.x * (NT/32) + (tid >> 5);
    int NW = gridDim.x * (NT/32);
    int gtid = blockIdx.x * NT + tid;
    int NTH = gridDim.x * NT;

    for (int u = 0; u < U_; u++) {
        const float* h_in  = hb + (u&1)*(B_*H_);     (void)h_in;
        float*       h_out = hb + ((u&1)^1)*(B_*H_);
        const float* c_in  = cb + (u&1)*(B_*H_);
        float*       c_out = cb + ((u&1)^1)*(B_*H_);
        const float* al_in  = alb + (u&1)*(T_*B_);
        float*       al_out = alb + ((u&1)^1)*(T_*B_);
        const float* eg_u = eg + (size_t)u*B_*G4H;
        float*       sc_u = scall + (size_t)u*B_*(2*E_);

        /* ---- Phase A: gates[b,r] = eg + ctx·Wihc[r] + h·Whh[r] (bf16 w+acts) ---- */
        for (int r = gw; r < G4H; r += NW) {
            float acc[16];
#pragma unroll
            for (int b = 0; b < 16; b++) acc[b] = 0.f;
            {
                const __nv_bfloat16* wr = wihc + (size_t)r * E_;
                for (int k = lane*8; k < E_; k += 256) {
                    float wv[8]; bf8(*(const float4*)(wr + k), wv);
#pragma unroll
                    for (int b = 0; b < 16; b++) {
                        float av[8]; bf8(*(const float4*)(ctxbf + b*E_ + k), av);
                        acc[b] += wv[0]*av[0]+wv[1]*av[1]+wv[2]*av[2]+wv[3]*av[3]
                                + wv[4]*av[4]+wv[5]*av[5]+wv[6]*av[6]+wv[7]*av[7];
                    }
                }
            }
            {
                const __nv_bfloat16* wr = whh + (size_t)r * H_;
                for (int k = lane*8; k < H_; k += 256) {
                    float wv[8]; bf8(*(const float4*)(wr + k), wv);
#pragma unroll
                    for (int b = 0; b < 16; b++) {
                        float av[8]; bf8(*(const float4*)(hbf + b*H_ + k), av);
                        acc[b] += wv[0]*av[0]+wv[1]*av[1]+wv[2]*av[2]+wv[3]*av[3]
                                + wv[4]*av[4]+wv[5]*av[5]+wv[6]*av[6]+wv[7]*av[7];
                    }
                }
            }
#pragma unroll
            for (int b = 0; b < 16; b++)
#pragma unroll
                for (int off = 16; off > 0; off >>= 1)
                    acc[b] += __shfl_xor_sync(0xffffffffu, acc[b], off);
            if (lane < 16)
                gates[(size_t)lane*G4H + r] = acc[lane] + eg_u[(size_t)lane*G4H + r];
        }
        gbar();

        /* ---- Phase B: LSTM pointwise; also write bf16 h ---- */
        for (int i = gtid; i < B_*H_; i += NTH) {
            int b = i >> 11, k = i & (H_-1);
            const float* g = gates + (size_t)b * G4H;
            float gi = g[k], gf = g[H_ + k], gg = g[2*H_ + k], go = g[3*H_ + k];
            float cn = sigm(gf) * c_in[i] + sigm(gi) * tanhf(gg);
            c_out[i] = cn;
            float hn = sigm(go) * tanhf(cn);
            h_out[i] = hn;
            hbf[i] = __float2bfloat16(hn);
        }
        gbar();

        /* ---- Phase C: s / sm / sc from h_new (fp32 weights, fold exact) ---- */
        for (int r = gw; r < 3*E_; r += NW) {
            const float* Wr = (r < E_) ? (wproj + (size_t)r * H_)
                                       : (comb + (size_t)(r - E_) * H_);
            float acc[16];
#pragma unroll
            for (int b = 0; b < 16; b++) acc[b] = 0.f;
            for (int k = lane*4; k < H_; k += 128) {
                float4 wv = *(const float4*)(Wr + k);
#pragma unroll
                for (int b = 0; b < 16; b++) {
                    float4 a = *(const float4*)(h_out + (size_t)b*H_ + k);
                    acc[b] += wv.x*a.x + wv.y*a.y + wv.z*a.z + wv.w*a.w;
                }
            }
#pragma unroll
            for (int b = 0; b < 16; b++)
#pragma unroll
                for (int off = 16; off > 0; off >>= 1)
                    acc[b] += __shfl_xor_sync(0xffffffffu, acc[b], off);
            if (lane < 16) {
                float v = acc[lane];
                if (r < E_)            sc_u[lane*(2*E_) + r] = v;
                else if (r < 2*E_)     smv[lane*E_ + (r - E_)] = v;
                else                   scv[lane*E_ + (r - 2*E_)] = v;
            }
        }
        gbar();

        /* ---- Phase D: energies ---- */
        for (int w = gw; w < T_*B_; w += NW) {
            int t = w >> 4, b = w & 15;
            const float* xmp = xh_m + (size_t)(t*B_ + b) * E_;
            const float* xcp = xh_c + (size_t)(t*B_ + b) * E_;
            const float* smp = smv + (size_t)b * E_;
            const float* scp = scv + (size_t)b * E_;
            float am = 0.f, ac = 0.f;
            for (int e = lane*4; e < E_; e += 128) {
                float4 a  = *(const float4*)(xmp + e);
                float4 s4 = *(const float4*)(smp + e);
                float4 v4 = *(const float4*)(v_m + e);
                am += v4.x*tanha(a.x+s4.x) + v4.y*tanha(a.y+s4.y)
                    + v4.z*tanha(a.z+s4.z) + v4.w*tanha(a.w+s4.w);
                float4 a2  = *(const float4*)(xcp + e);
                float4 s42 = *(const float4*)(scp + e);
                float4 v42 = *(const float4*)(v_c + e);
                ac += v42.x*tanha(a2.x+s42.x) + v42.y*tanha(a2.y+s42.y)
                    + v42.z*tanha(a2.z+s42.z) + v42.w*tanha(a2.w+s42.w);
            }
#pragma unroll
            for (int off = 16; off > 0; off >>= 1) {
                am += __shfl_xor_sync(0xffffffffu, am, off);
                ac += __shfl_xor_sync(0xffffffffu, ac, off);
            }
            if (lane == 0) {
                float mk = mask[b*T_ + t];
                pv[t*B_ + b] = sigm(am + r_m[0]) * mk;
                uvv[t*B_ + b] = ac;
            }
        }
        gbar();

        /* ---- Phase E: per-b scans (blocks 0..15) ---- */
        if (blockIdx.x < B_) {
            int b = blockIdx.x, t = tid;
            float pvv = pv[t*B_ + b];
            float uvl = uvv[t*B_ + b];
            float ap  = al_in[t*B_ + b];
            float mk  = mask[b*T_ + t];

            shR[t] = uvl; __syncthreads();
            for (int off = 128; off > 0; off >>= 1) {
                if (t < off) shR[t] = fmaxf(shR[t], shR[t+off]);
                __syncthreads();
            }
            float um = shR[0];

            float eu = expf(uvl - um) * mk;
            shA[t] = eu; __syncthreads();
#pragma unroll
            for (int off = 1; off < T_; off <<= 1) {
                float xv = (t >= off) ? shA[t-off] : 0.f;
                __syncthreads(); shA[t] += xv; __syncthreads();
            }
            float denom = shA[t] - (t >= 8 ? shA[t-8] : 0.f);

            shB[t] = 1.f - pvv; __syncthreads();
#pragma unroll
            for (int off = 1; off < T_; off <<= 1) {
                float xv = (t >= off) ? shB[t-off] : 1.f;
                __syncthreads(); shB[t] *= xv; __syncthreads();
            }
            float cp = (t == 0) ? 1.f : shB[t-1];

            shC[t] = ap / fmaxf(cp, EPS_); __syncthreads();
#pragma unroll
            for (int off = 1; off < T_; off <<= 1) {
                float xv = (t >= off) ? shC[t-off] : 0.f;
                __syncthreads(); shC[t] += xv; __syncthreads();
            }
            float av = pvv * cp * shC[t];

            shD[t] = av / fmaxf(denom, EPS_); __syncthreads();
#pragma unroll
            for (int off = 1; off < T_; off <<= 1) {
                float xv = (t >= off) ? shD[t-off] : 0.f;
                __syncthreads(); shD[t] += xv; __syncthreads();
            }
            int hi = (t + 7 > T_-1) ? (T_-1) : (t + 7);
            float bv = eu * (shD[hi] - (t > 0 ? shD[t-1] : 0.f));

            al_out[t*B_ + b] = av;
            betav[t*B_ + b] = bv;
        }
        gbar();

        /* ---- Phase F: ctx[b,d] = sum_t beta * x; write scall + bf16 ctx ---- */
        for (int i = gtid; i < B_*E_; i += NTH) {
            int b = i >> 9, d = i & (E_-1);
            const float* xp = x + (size_t)b*E_ + d;
            float acc = 0.f;
#pragma unroll 8
            for (int t = 0; t < T_; t++)
                acc += betav[t*B_ + b] * xp[(size_t)t * B_ * E_];
            sc_u[(size_t)b*(2*E_) + E_ + d] = acc;
            ctxbf[i] = __float2bfloat16(acc);
        }
        gbar();
    }
}

/* ---------------- host launcher ---------------- */
extern "C" void kernel_launch(void* const* d_in, const int* in_sizes, int n_in,
                              void* d_out, int out_size)
{
    const float* x        = (const float*)d_in[0];
    const float* att_mask = (const float*)d_in[1];
    const float* emb_tab  = (const float*)d_in[2];
    const float* W_ih     = (const float*)d_in[3];
    const float* W_hh     = (const float*)d_in[4];
    const float* b_lstm   = (const float*)d_in[5];
    const float* W_proj   = (const float*)d_in[6];
    const float* Ws_m     = (const float*)d_in[7];
    const float* Wh_m     = (const float*)d_in[8];
    const float* v_m      = (const float*)d_in[9];
    const float* r_m      = (const float*)d_in[10];
    const float* Ws_c     = (const float*)d_in[11];
    const float* Wh_c     = (const float*)d_in[12];
    const float* v_c      = (const float*)d_in[13];
    const float* W_am     = (const float*)d_in[14];
    const float* W_lm     = (const float*)d_in[15];
    const int*   label    = (const int*)d_in[16];

    float* out_am = (float*)d_out;
    float* out_lm = out_am + (size_t)N_ * U_ * B_;

    float *xh_m, *xh_c, *emb, *eg, *gates, *hb, *cb, *alb, *sm, *sc, *p, *uu, *beta, *scall, *wpT, *comb;
    __nv_bfloat16 *whh_bf, *wihc_bf, *hbf, *ctxbf;
    cudaGetSymbolAddress((void**)&xh_m,  g_xh_m);
    cudaGetSymbolAddress((void**)&xh_c,  g_xh_c);
    cudaGetSymbolAddress((void**)&emb,   g_emb);
    cudaGetSymbolAddress((void**)&eg,    g_eg);
    cudaGetSymbolAddress((void**)&gates, g_gates);
    cudaGetSymbolAddress((void**)&hb,    g_h);
    cudaGetSymbolAddress((void**)&cb,    g_c);
    cudaGetSymbolAddress((void**)&alb,   g_alpha);
    cudaGetSymbolAddress((void**)&sm,    g_sm);
    cudaGetSymbolAddress((void**)&sc,    g_sc);
    cudaGetSymbolAddress((void**)&p,     g_p);
    cudaGetSymbolAddress((void**)&uu,    g_u);
    cudaGetSymbolAddress((void**)&beta,  g_beta);
    cudaGetSymbolAddress((void**)&scall, g_scall);
    cudaGetSymbolAddress((void**)&wpT,   g_wpT);
    cudaGetSymbolAddress((void**)&comb,  g_comb);
    cudaGetSymbolAddress((void**)&whh_bf,  g_whh_bf);
    cudaGetSymbolAddress((void**)&wihc_bf, g_wihc_bf);
    cudaGetSymbolAddress((void**)&hbf,   g_hbf);
    cudaGetSymbolAddress((void**)&ctxbf, g_ctxbf);

    init_state<<<(2*B_*H_ + 255)/256, 256>>>(hb, cb, alb, hbf, ctxbf);

    /* bf16 weight conversions */
    {
        size_t n;
        n = (size_t)G4H*H_; f2bf<<<(int)((n+511)/512), 512>>>(W_hh, whh_bf, n);
        n = (size_t)G4H*E_; f2bf_strided<<<(int)((n+511)/512), 512>>>(W_ih, 2*E_, E_, wihc_bf, E_, n);
    }

    gather_emb<<<U_*B_, 128>>>(emb_tab, label, emb);

    /* encoder-side projections */
    sgemm_tn<<<dim3((T_*B_)/BN, (E_+BM-1)/BM), 256>>>(Wh_m, E_, x, E_, nullptr,
            xh_m, 1, E_, E_, T_*B_, E_);
    sgemm_tn<<<dim3((T_*B_)/BN, (E_+BM-1)/BM), 256>>>(Wh_c, E_, x, E_, nullptr,
            xh_c, 1, E_, E_, T_*B_, E_);

    /* eg = emb @ W_ih[:, :E]^T + b_lstm */
    sgemm_tn<<<dim3((U_*B_)/BN, G4H/BM), 256>>>(W_ih, 2*E_, emb, E_, b_lstm,
            eg, 1, G4H, G4H, U_*B_, E_);

    /* lm output */
    sgemm_tn<<<dim3((U_*B_)/BN, (N_+BM-1)/BM), 256>>>(W_lm, E_, emb, E_, nullptr,
            out_lm, U_*B_, 1, N_, U_*B_, E_);

    /* exact fp32 folds: comb = [Ws_m@W_proj ; Ws_c@W_proj] */
    transposeEH<<<dim3(H_/32, E_/32), dim3(32, 8)>>>(W_proj, wpT);
    sgemm_tn<<<dim3(H_/BN, E_/BM), 256>>>(Ws_m, E_, wpT, E_, nullptr,
            comb, H_, 1, E_, H_, E_);
    sgemm_tn<<<dim3(H_/BN, E_/BM), 256>>>(Ws_c, E_, wpT, E_, nullptr,
            comb + (size_t)E_*H_, H_, 1, E_, H_, E_);

    /* the whole 48-step recurrence in ONE persistent kernel */
    decoder_loop<<<GRID, NT>>>(x, att_mask, whh_bf, wihc_bf, W_proj, comb,
            eg, v_m, v_c, r_m, xh_m, xh_c,
            gates, hb, cb, alb, hbf, ctxbf,
            sm, sc, p, uu, beta, scall);

    /* am output */
    sgemm_tn<<<dim3((U_*B_)/BN, (N_+BM-1)/BM), 256>>>(W_am, 2*E_, scall, 2*E_, nullptr,
            out_am, U_*B_, 1, N_, U_*B_, 2*E_);
}

// round 7
// speedup vs baseline: 1.8197x; 1.2024x over previous
#include <cuda_runtime.h>
#include <cuda_bf16.h>
#include <math.h>

#define T_ 256
#define B_ 16
#define E_ 512
#define H_ 2048
#define N_ 14839
#define U_ 48
#define G4H 8192
#define EPS_ 1e-6f
#define NT 256
#define GRID 256

/* ---------------- scratch ---------------- */
__device__ float g_xh_m[T_*B_*E_];
__device__ float g_xh_c[T_*B_*E_];
__device__ float g_emb[U_*B_*E_];
__device__ float g_eg[(size_t)U_*B_*G4H];
__device__ float g_gates[(size_t)B_*G4H];
__device__ float g_h[2][B_*H_];
__device__ float g_c[2][B_*H_];
__device__ float g_alpha[2][T_*B_];
__device__ float g_sm[B_*E_];
__device__ float g_sc[B_*E_];
__device__ float g_p[T_*B_];
__device__ float g_u[T_*B_];
__device__ float g_beta[T_*B_];
__device__ float g_scall[U_*B_*2*E_];
__device__ float g_wpT[H_*E_];
__device__ float g_comb[2*E_*H_];
__device__ __nv_bfloat16 g_whh_bf[(size_t)G4H*H_];
__device__ __nv_bfloat16 g_wihc_bf[(size_t)G4H*E_];
__device__ __nv_bfloat16 g_hbf[B_*H_];
__device__ __nv_bfloat16 g_ctxbf[B_*E_];

/* grid barrier state */
__device__ unsigned g_cnt = 0;
__device__ volatile unsigned g_gen = 0;

__device__ __forceinline__ void gbar() {
    __syncthreads();
    if (threadIdx.x == 0) {
        unsigned gen = g_gen;
        __threadfence();
        if (atomicAdd(&g_cnt, 1u) == gridDim.x - 1u) {
            g_cnt = 0;
            __threadfence();
            g_gen = gen + 1u;
        } else {
            while (g_gen == gen) __nanosleep(32);
        }
        __threadfence();
    }
    __syncthreads();
}

__device__ __forceinline__ float sigm(float x) { return 1.f / (1.f + expf(-x)); }
__device__ __forceinline__ float tanha(float x) {
    float y; asm("tanh.approx.f32 %0, %1;" : "=f"(y) : "f"(x)); return y;
}
__device__ __forceinline__ void bf8(float4 raw, float* o) {
    const __nv_bfloat162* p = (const __nv_bfloat162*)&raw;
    float2 a = __bfloat1622float2(p[0]); float2 b = __bfloat1622float2(p[1]);
    float2 c = __bfloat1622float2(p[2]); float2 d = __bfloat1622float2(p[3]);
    o[0]=a.x;o[1]=a.y;o[2]=b.x;o[3]=b.y;o[4]=c.x;o[5]=c.y;o[6]=d.x;o[7]=d.y;
}
__device__ __forceinline__ unsigned tf32c(float x) {
    unsigned r; asm("cvt.rna.tf32.f32 %0, %1;" : "=r"(r) : "f"(x)); return r;
}

/* ---------------- init ---------------- */
__global__ void init_state(float* h, float* c, float* alpha,
                           __nv_bfloat16* hbf, __nv_bfloat16* ctxbf) {
    int i = blockIdx.x * blockDim.x + threadIdx.x;
    if (i < 2*B_*H_) { h[i] = 0.f; c[i] = 0.f; }
    if (i < B_*H_)   hbf[i] = __float2bfloat16(0.f);
    if (i < B_*E_)   ctxbf[i] = __float2bfloat16(0.f);
    if (i < T_*B_)   alpha[i] = (i < B_) ? 1.f : 0.f;
}

/* ---------------- conversions ---------------- */
__global__ void f2bf(const float* __restrict__ src, __nv_bfloat16* __restrict__ dst, size_t n) {
    size_t i = (size_t)blockIdx.x * blockDim.x + threadIdx.x;
    if (i < n) dst[i] = __float2bfloat16(src[i]);
}
__global__ void f2bf_strided(const float* __restrict__ src, int ld, int off,
                             __nv_bfloat16* __restrict__ dst, int cols, size_t n) {
    size_t i = (size_t)blockIdx.x * blockDim.x + threadIdx.x;
    if (i >= n) return;
    size_t r = i / cols, c = i % cols;
    dst[i] = __float2bfloat16(src[r * (size_t)ld + off + c]);
}

/* ---------------- embedding gather ---------------- */
__global__ void gather_emb(const float* __restrict__ emb_table,
                           const int* __restrict__ label,
                           float* __restrict__ emb) {
    int r = blockIdx.x;
    int n = label[r];
    const float* src = emb_table + (size_t)n * E_;
    float* dst = emb + (size_t)r * E_;
    for (int i = threadIdx.x; i < E_; i += blockDim.x) dst[i] = src[i];
}

/* ---------------- transpose (512,2048) -> (2048,512) ---------------- */
__global__ void transposeEH(const float* __restrict__ A, float* __restrict__ At) {
    __shared__ float tile[32][33];
    int x0 = blockIdx.x * 32, y0 = blockIdx.y * 32;
    int tx = threadIdx.x, ty = threadIdx.y;
    for (int j = 0; j < 32; j += 8)
        tile[ty+j][tx] = A[(size_t)(y0+ty+j) * H_ + x0 + tx];
    __syncthreads();
    for (int j = 0; j < 32; j += 8)
        At[(size_t)(x0+ty+j) * E_ + y0 + tx] = tile[tx][ty+j];
}

/* ============ tf32 tensor-core GEMM: C[m,j] = sum_k W[m,k]*X[j,k] (+bias[m]) ============
   Block tile 128(M) x 64(N), 8 warps in 4x2 grid of 32x32 warp tiles.
   mma.sync.aligned.m16n8k8.row.col.f32.tf32.tf32.f32. K must be a multiple of 32.      */
#define TKC 32
#define TKP (TKC+4)
__global__ __launch_bounds__(256) void tgemm_tn(
        const float* __restrict__ W, int ldw,
        const float* __restrict__ X, int ldx,
        const float* __restrict__ bias,
        float* __restrict__ C, size_t ldcw, size_t ldcx,
        int M, int Nx, int K)
{
    __shared__ unsigned Ws[128][TKP];
    __shared__ unsigned Xs[64][TKP];
    int tid = threadIdx.x;
    int wid = tid >> 5, lane = tid & 31;
    int wm = (wid & 3) * 32;          // warp M offset
    int wn = (wid >> 2) * 32;         // warp N offset
    int m0 = blockIdx.y * 128;
    int n0 = blockIdx.x * 64;
    int g = lane >> 2, t = lane & 3;

    float c[2][4][4];
#pragma unroll
    for (int i = 0; i < 2; i++)
#pragma unroll
        for (int j = 0; j < 4; j++)
#pragma unroll
            for (int q = 0; q < 4; q++) c[i][j][q] = 0.f;

    for (int k0 = 0; k0 < K; k0 += TKC) {
        /* stage W tile (128 x 32): 4 float4 per thread */
        {
            int r = tid >> 1;
            int cc = (tid & 1) * 16;
#pragma unroll
            for (int i = 0; i < 4; i++) {
                float4 v = make_float4(0.f,0.f,0.f,0.f);
                if (m0 + r < M)
                    v = *(const float4*)(W + (size_t)(m0 + r) * ldw + k0 + cc + i*4);
                Ws[r][cc+i*4+0] = tf32c(v.x); Ws[r][cc+i*4+1] = tf32c(v.y);
                Ws[r][cc+i*4+2] = tf32c(v.z); Ws[r][cc+i*4+3] = tf32c(v.w);
            }
        }
        /* stage X tile (64 x 32): 2 float4 per thread */
        {
            int r = tid >> 2;
            int cc = (tid & 3) * 8;
#pragma unroll
            for (int i = 0; i < 2; i++) {
                float4 v = make_float4(0.f,0.f,0.f,0.f);
                if (n0 + r < Nx)
                    v = *(const float4*)(X + (size_t)(n0 + r) * ldx + k0 + cc + i*4);
                Xs[r][cc+i*4+0] = tf32c(v.x); Xs[r][cc+i*4+1] = tf32c(v.y);
                Xs[r][cc+i*4+2] = tf32c(v.z); Xs[r][cc+i*4+3] = tf32c(v.w);
            }
        }
        __syncthreads();

#pragma unroll
        for (int kk = 0; kk < TKC; kk += 8) {
            unsigned a[2][4];
#pragma unroll
            for (int mt = 0; mt < 2; mt++) {
                int br = wm + mt*16;
                a[mt][0] = Ws[br + g    ][kk + t];
                a[mt][1] = Ws[br + g + 8][kk + t];
                a[mt][2] = Ws[br + g    ][kk + t + 4];
                a[mt][3] = Ws[br + g + 8][kk + t + 4];
            }
            unsigned b[4][2];
#pragma unroll
            for (int nt = 0; nt < 4; nt++) {
                b[nt][0] = Xs[wn + nt*8 + g][kk + t];
                b[nt][1] = Xs[wn + nt*8 + g][kk + t + 4];
            }
#pragma unroll
            for (int mt = 0; mt < 2; mt++)
#pragma unroll
                for (int nt = 0; nt < 4; nt++) {
                    asm volatile(
                        "mma.sync.aligned.m16n8k8.row.col.f32.tf32.tf32.f32 "
                        "{%0,%1,%2,%3}, {%4,%5,%6,%7}, {%8,%9}, {%0,%1,%2,%3};"
                        : "+f"(c[mt][nt][0]), "+f"(c[mt][nt][1]),
                          "+f"(c[mt][nt][2]), "+f"(c[mt][nt][3])
                        : "r"(a[mt][0]), "r"(a[mt][1]), "r"(a[mt][2]), "r"(a[mt][3]),
                          "r"(b[nt][0]), "r"(b[nt][1]));
                }
        }
        __syncthreads();
    }

    /* epilogue */
#pragma unroll
    for (int mt = 0; mt < 2; mt++) {
#pragma unroll
        for (int nt = 0; nt < 4; nt++) {
            int row0 = m0 + wm + mt*16 + g;
            int col0 = n0 + wn + nt*8 + 2*t;
#pragma unroll
            for (int half = 0; half < 2; half++) {
                int row = row0 + half*8;
                if (row >= M) continue;
                float bv = bias ? bias[row] : 0.f;
                if (col0 < Nx)
                    C[(size_t)row*ldcw + (size_t)col0*ldcx] = c[mt][nt][half*2+0] + bv;
                if (col0 + 1 < Nx)
                    C[(size_t)row*ldcw + (size_t)(col0+1)*ldcx] = c[mt][nt][half*2+1] + bv;
            }
        }
    }
}

/* ================ PERSISTENT DECODER LOOP (unchanged from R6) ================ */
__global__ __launch_bounds__(NT) void decoder_loop(
        const float* __restrict__ x, const float* __restrict__ mask,
        const __nv_bfloat16* __restrict__ whh, const __nv_bfloat16* __restrict__ wihc,
        const float* __restrict__ wproj, const float* __restrict__ comb,
        const float* __restrict__ eg,
        const float* __restrict__ v_m, const float* __restrict__ v_c,
        const float* __restrict__ r_m,
        const float* __restrict__ xh_m, const float* __restrict__ xh_c,
        float* gates, float* hb, float* cb, float* alb,
        __nv_bfloat16* hbf, __nv_bfloat16* ctxbf,
        float* smv, float* scv, float* pv, float* uvv, float* betav,
        float* scall)
{
    __shared__ float shA[T_], shB[T_], shC[T_], shD[T_], shR[T_];
    int tid = threadIdx.x;
    int lane = tid & 31;
    int gw = blockIdx.x * (NT/32) + (tid >> 5);
    int NW = gridDim.x * (NT/32);
    int gtid = blockIdx.x * NT + tid;
    int NTH = gridDim.x * NT;

    for (int u = 0; u < U_; u++) {
        float*       h_out = hb + ((u&1)^1)*(B_*H_);
        const float* c_in  = cb + (u&1)*(B_*H_);
        float*       c_out = cb + ((u&1)^1)*(B_*H_);
        const float* al_in  = alb + (u&1)*(T_*B_);
        float*       al_out = alb + ((u&1)^1)*(T_*B_);
        const float* eg_u = eg + (size_t)u*B_*G4H;
        float*       sc_u = scall + (size_t)u*B_*(2*E_);

        /* ---- Phase A: gates ---- */
        for (int r = gw; r < G4H; r += NW) {
            float acc[16];
#pragma unroll
            for (int b = 0; b < 16; b++) acc[b] = 0.f;
            {
                const __nv_bfloat16* wr = wihc + (size_t)r * E_;
                for (int k = lane*8; k < E_; k += 256) {
                    float wv[8]; bf8(*(const float4*)(wr + k), wv);
#pragma unroll
                    for (int b = 0; b < 16; b++) {
                        float av[8]; bf8(*(const float4*)(ctxbf + b*E_ + k), av);
                        acc[b] += wv[0]*av[0]+wv[1]*av[1]+wv[2]*av[2]+wv[3]*av[3]
                                + wv[4]*av[4]+wv[5]*av[5]+wv[6]*av[6]+wv[7]*av[7];
                    }
                }
            }
            {
                const __nv_bfloat16* wr = whh + (size_t)r * H_;
                for (int k = lane*8; k < H_; k += 256) {
                    float wv[8]; bf8(*(const float4*)(wr + k), wv);
#pragma unroll
                    for (int b = 0; b < 16; b++) {
                        float av[8]; bf8(*(const float4*)(hbf + b*H_ + k), av);
                        acc[b] += wv[0]*av[0]+wv[1]*av[1]+wv[2]*av[2]+wv[3]*av[3]
                                + wv[4]*av[4]+wv[5]*av[5]+wv[6]*av[6]+wv[7]*av[7];
                    }
                }
            }
#pragma unroll
            for (int b = 0; b < 16; b++)
#pragma unroll
                for (int off = 16; off > 0; off >>= 1)
                    acc[b] += __shfl_xor_sync(0xffffffffu, acc[b], off);
            if (lane < 16)
                gates[(size_t)lane*G4H + r] = acc[lane] + eg_u[(size_t)lane*G4H + r];
        }
        gbar();

        /* ---- Phase B: LSTM pointwise ---- */
        for (int i = gtid; i < B_*H_; i += NTH) {
            int b = i >> 11, k = i & (H_-1);
            const float* g = gates + (size_t)b * G4H;
            float gi = g[k], gf = g[H_ + k], gg = g[2*H_ + k], go = g[3*H_ + k];
            float cn = sigm(gf) * c_in[i] + sigm(gi) * tanhf(gg);
            c_out[i] = cn;
            float hn = sigm(go) * tanhf(cn);
            h_out[i] = hn;
            hbf[i] = __float2bfloat16(hn);
        }
        gbar();

        /* ---- Phase C: s / sm / sc ---- */
        for (int r = gw; r < 3*E_; r += NW) {
            const float* Wr = (r < E_) ? (wproj + (size_t)r * H_)
                                       : (comb + (size_t)(r - E_) * H_);
            float acc[16];
#pragma unroll
            for (int b = 0; b < 16; b++) acc[b] = 0.f;
            for (int k = lane*4; k < H_; k += 128) {
                float4 wv = *(const float4*)(Wr + k);
#pragma unroll
                for (int b = 0; b < 16; b++) {
                    float4 a = *(const float4*)(h_out + (size_t)b*H_ + k);
                    acc[b] += wv.x*a.x + wv.y*a.y + wv.z*a.z + wv.w*a.w;
                }
            }
#pragma unroll
            for (int b = 0; b < 16; b++)
#pragma unroll
                for (int off = 16; off > 0; off >>= 1)
                    acc[b] += __shfl_xor_sync(0xffffffffu, acc[b], off);
            if (lane < 16) {
                float v = acc[lane];
                if (r < E_)            sc_u[lane*(2*E_) + r] = v;
                else if (r < 2*E_)     smv[lane*E_ + (r - E_)] = v;
                else                   scv[lane*E_ + (r - 2*E_)] = v;
            }
        }
        gbar();

        /* ---- Phase D: energies ---- */
        for (int w = gw; w < T_*B_; w += NW) {
            int t = w >> 4, b = w & 15;
            const float* xmp = xh_m + (size_t)(t*B_ + b) * E_;
            const float* xcp = xh_c + (size_t)(t*B_ + b) * E_;
            const float* smp = smv + (size_t)b * E_;
            const float* scp = scv + (size_t)b * E_;
            float am = 0.f, ac = 0.f;
            for (int e = lane*4; e < E_; e += 128) {
                float4 a  = *(const float4*)(xmp + e);
                float4 s4 = *(const float4*)(smp + e);
                float4 v4 = *(const float4*)(v_m + e);
                am += v4.x*tanha(a.x+s4.x) + v4.y*tanha(a.y+s4.y)
                    + v4.z*tanha(a.z+s4.z) + v4.w*tanha(a.w+s4.w);
                float4 a2  = *(const float4*)(xcp + e);
                float4 s42 = *(const float4*)(scp + e);
                float4 v42 = *(const float4*)(v_c + e);
                ac += v42.x*tanha(a2.x+s42.x) + v42.y*tanha(a2.y+s42.y)
                    + v42.z*tanha(a2.z+s42.z) + v42.w*tanha(a2.w+s42.w);
            }
#pragma unroll
            for (int off = 16; off > 0; off >>= 1) {
                am += __shfl_xor_sync(0xffffffffu, am, off);
                ac += __shfl_xor_sync(0xffffffffu, ac, off);
            }
            if (lane == 0) {
                float mk = mask[b*T_ + t];
                pv[t*B_ + b] = sigm(am + r_m[0]) * mk;
                uvv[t*B_ + b] = ac;
            }
        }
        gbar();

        /* ---- Phase E: per-b scans ---- */
        if (blockIdx.x < B_) {
            int b = blockIdx.x, t = tid;
            float pvv = pv[t*B_ + b];
            float uvl = uvv[t*B_ + b];
            float ap  = al_in[t*B_ + b];
            float mk  = mask[b*T_ + t];

            shR[t] = uvl; __syncthreads();
            for (int off = 128; off > 0; off >>= 1) {
                if (t < off) shR[t] = fmaxf(shR[t], shR[t+off]);
                __syncthreads();
            }
            float um = shR[0];

            float eu = expf(uvl - um) * mk;
            shA[t] = eu; __syncthreads();
#pragma unroll
            for (int off = 1; off < T_; off <<= 1) {
                float xv = (t >= off) ? shA[t-off] : 0.f;
                __syncthreads(); shA[t] += xv; __syncthreads();
            }
            float denom = shA[t] - (t >= 8 ? shA[t-8] : 0.f);

            shB[t] = 1.f - pvv; __syncthreads();
#pragma unroll
            for (int off = 1; off < T_; off <<= 1) {
                float xv = (t >= off) ? shB[t-off] : 1.f;
                __syncthreads(); shB[t] *= xv; __syncthreads();
            }
            float cp = (t == 0) ? 1.f : shB[t-1];

            shC[t] = ap / fmaxf(cp, EPS_); __syncthreads();
#pragma unroll
            for (int off = 1; off < T_; off <<= 1) {
                float xv = (t >= off) ? shC[t-off] : 0.f;
                __syncthreads(); shC[t] += xv; __syncthreads();
            }
            float av = pvv * cp * shC[t];

            shD[t] = av / fmaxf(denom, EPS_); __syncthreads();
#pragma unroll
            for (int off = 1; off < T_; off <<= 1) {
                float xv = (t >= off) ? shD[t-off] : 0.f;
                __syncthreads(); shD[t] += xv; __syncthreads();
            }
            int hi = (t + 7 > T_-1) ? (T_-1) : (t + 7);
            float bv = eu * (shD[hi] - (t > 0 ? shD[t-1] : 0.f));

            al_out[t*B_ + b] = av;
            betav[t*B_ + b] = bv;
        }
        gbar();

        /* ---- Phase F: ctx ---- */
        for (int i = gtid; i < B_*E_; i += NTH) {
            int b = i >> 9, d = i & (E_-1);
            const float* xp = x + (size_t)b*E_ + d;
            float acc = 0.f;
#pragma unroll 8
            for (int t = 0; t < T_; t++)
                acc += betav[t*B_ + b] * xp[(size_t)t * B_ * E_];
            sc_u[(size_t)b*(2*E_) + E_ + d] = acc;
            ctxbf[i] = __float2bfloat16(acc);
        }
        gbar();
    }
}

/* ---------------- host launcher ---------------- */
extern "C" void kernel_launch(void* const* d_in, const int* in_sizes, int n_in,
                              void* d_out, int out_size)
{
    const float* x        = (const float*)d_in[0];
    const float* att_mask = (const float*)d_in[1];
    const float* emb_tab  = (const float*)d_in[2];
    const float* W_ih     = (const float*)d_in[3];
    const float* W_hh     = (const float*)d_in[4];
    const float* b_lstm   = (const float*)d_in[5];
    const float* W_proj   = (const float*)d_in[6];
    const float* Ws_m     = (const float*)d_in[7];
    const float* Wh_m     = (const float*)d_in[8];
    const float* v_m      = (const float*)d_in[9];
    const float* r_m      = (const float*)d_in[10];
    const float* Ws_c     = (const float*)d_in[11];
    const float* Wh_c     = (const float*)d_in[12];
    const float* v_c      = (const float*)d_in[13];
    const float* W_am     = (const float*)d_in[14];
    const float* W_lm     = (const float*)d_in[15];
    const int*   label    = (const int*)d_in[16];

    float* out_am = (float*)d_out;
    float* out_lm = out_am + (size_t)N_ * U_ * B_;

    float *xh_m, *xh_c, *emb, *eg, *gates, *hb, *cb, *alb, *sm, *sc, *p, *uu, *beta, *scall, *wpT, *comb;
    __nv_bfloat16 *whh_bf, *wihc_bf, *hbf, *ctxbf;
    cudaGetSymbolAddress((void**)&xh_m,  g_xh_m);
    cudaGetSymbolAddress((void**)&xh_c,  g_xh_c);
    cudaGetSymbolAddress((void**)&emb,   g_emb);
    cudaGetSymbolAddress((void**)&eg,    g_eg);
    cudaGetSymbolAddress((void**)&gates, g_gates);
    cudaGetSymbolAddress((void**)&hb,    g_h);
    cudaGetSymbolAddress((void**)&cb,    g_c);
    cudaGetSymbolAddress((void**)&alb,   g_alpha);
    cudaGetSymbolAddress((void**)&sm,    g_sm);
    cudaGetSymbolAddress((void**)&sc,    g_sc);
    cudaGetSymbolAddress((void**)&p,     g_p);
    cudaGetSymbolAddress((void**)&uu,    g_u);
    cudaGetSymbolAddress((void**)&beta,  g_beta);
    cudaGetSymbolAddress((void**)&scall, g_scall);
    cudaGetSymbolAddress((void**)&wpT,   g_wpT);
    cudaGetSymbolAddress((void**)&comb,  g_comb);
    cudaGetSymbolAddress((void**)&whh_bf,  g_whh_bf);
    cudaGetSymbolAddress((void**)&wihc_bf, g_wihc_bf);
    cudaGetSymbolAddress((void**)&hbf,   g_hbf);
    cudaGetSymbolAddress((void**)&ctxbf, g_ctxbf);

    init_state<<<(2*B_*H_ + 255)/256, 256>>>(hb, cb, alb, hbf, ctxbf);

    {
        size_t n;
        n = (size_t)G4H*H_; f2bf<<<(int)((n+511)/512), 512>>>(W_hh, whh_bf, n);
        n = (size_t)G4H*E_; f2bf_strided<<<(int)((n+511)/512), 512>>>(W_ih, 2*E_, E_, wihc_bf, E_, n);
    }

    gather_emb<<<U_*B_, 128>>>(emb_tab, label, emb);

    /* encoder-side projections (tf32 tensor GEMM) */
    tgemm_tn<<<dim3((T_*B_+63)/64, (E_+127)/128), 256>>>(Wh_m, E_, x, E_, nullptr,
            xh_m, 1, E_, E_, T_*B_, E_);
    tgemm_tn<<<dim3((T_*B_+63)/64, (E_+127)/128), 256>>>(Wh_c, E_, x, E_, nullptr,
            xh_c, 1, E_, E_, T_*B_, E_);

    /* eg = emb @ W_ih[:, :E]^T + b_lstm */
    tgemm_tn<<<dim3((U_*B_+63)/64, (G4H+127)/128), 256>>>(W_ih, 2*E_, emb, E_, b_lstm,
            eg, 1, G4H, G4H, U_*B_, E_);

    /* lm output */
    tgemm_tn<<<dim3((U_*B_+63)/64, (N_+127)/128), 256>>>(W_lm, E_, emb, E_, nullptr,
            out_lm, U_*B_, 1, N_, U_*B_, E_);

    /* fp32->tf32 folds: comb = [Ws_m@W_proj ; Ws_c@W_proj] */
    transposeEH<<<dim3(H_/32, E_/32), dim3(32, 8)>>>(W_proj, wpT);
    tgemm_tn<<<dim3((H_+63)/64, (E_+127)/128), 256>>>(Ws_m, E_, wpT, E_, nullptr,
            comb, H_, 1, E_, H_, E_);
    tgemm_tn<<<dim3((H_+63)/64, (E_+127)/128), 256>>>(Ws_c, E_, wpT, E_, nullptr,
            comb + (size_t)E_*H_, H_, 1, E_, H_, E_);

    /* 48-step recurrence in one persistent kernel */
    decoder_loop<<<GRID, NT>>>(x, att_mask, whh_bf, wihc_bf, W_proj, comb,
            eg, v_m, v_c, r_m, xh_m, xh_c,
            gates, hb, cb, alb, hbf, ctxbf,
            sm, sc, p, uu, beta, scall);

    /* am output */
    tgemm_tn<<<dim3((U_*B_+63)/64, (N_+127)/128), 256>>>(W_am, 2*E_, scall, 2*E_, nullptr,
            out_am, U_*B_, 1, N_, U_*B_, 2*E_);
}